// round 11
// baseline (speedup 1.0000x reference)
#include <cuda_runtime.h>
#include <math.h>

// Problem constants
#define BB   8
#define HW   14400   // 120*120
#define WATT 120
#define NP   10
#define PH   100
#define PW   100
#define CC   3
#define HH   1024
#define WHI  1024

#define CH    30       // chunks per batch
#define CHUNK 480      // elements per chunk (32 lanes x 15)
#define NC    (CH*NP)  // 300 candidates per batch

// d_out layout (flattened return tuple, all f32):
//   [0, 2400000)            patches (B,N,100,100,3)
//   [2400000, 2400080)      sampled_attention (B,N)
//   [2400080, 2400240)      offsets (B,N,2)
//   [2400240, 2400400)      samples (B,N,2) as float
#define PATCH_ELEMS (BB*NP*PH*PW*CC)   // 2,400,000
#define ROW_VEC     75                 // 300 floats per patch row = 75 float4
#define TOTAL_VEC   (PATCH_ELEMS/4)    // 600,000
#define GUNROLL     8
#define GSTRIDE     (TOTAL_VEC/GUNROLL)  // 75,000

#define SBLK  30       // score blocks (30 x 8 warps = 240 chunks)
#define FULL  0xffffffffu

__device__ int      g_corners[BB * NP * 2];
__device__ unsigned g_ckey[BB * NC];
__device__ int      g_cidx[BB * NC];
__device__ int      g_done = 0;

// order-preserving float->u32 key (all keys here are positive floats);
// poison value 0u is below every real key.
__device__ __forceinline__ unsigned f2key(float f) {
    unsigned x = __float_as_uint(f);
    return x ^ ((unsigned)(((int)x) >> 31) | 0x80000000u);
}

// ---------------------------------------------------------------------------
// Kernel A: score (ratio key, ordering-equivalent to the Gumbel score) +
// per-chunk top-10; the LAST finishing block merges all batches (no spin).
// ---------------------------------------------------------------------------
__global__ void __launch_bounds__(256, 1)
score_merge_kernel(const float* __restrict__ att,
                   const float* __restrict__ u,
                   float* __restrict__ out)
{
    const int tid  = threadIdx.x;
    const int lane = tid & 31;
    const int warp = tid >> 5;

    const int wg   = blockIdx.x * 8 + warp;   // 0..239
    const int b    = wg / CH;
    const int ch   = wg % CH;
    const int base = ch * CHUNK;

    const float* a  = att + b * HW;
    const float* uu = u   + b * HW;

    // ordering key:  log(max(a,1e-20)) - log(-log(clip(u))) is monotonic in
    //   max(a,1e-20) / (-log(clip(u)))   (numerator, denominator both > 0)
    // so key on the ratio directly: 2 MUFU ops instead of 3 logf's.
    unsigned lv[16];
    #pragma unroll
    for (int j = 0; j < 15; j++) {
        int i = base + j * 32 + lane;
        float uv = fminf(fmaxf(uu[i], 1e-6f), 1.0f - 1e-6f);
        float r  = __fdividef(fmaxf(a[i], 1e-20f), -__logf(uv));
        lv[j] = f2key(r);
    }
    lv[15] = 0u;

    #pragma unroll 1
    for (int k = 0; k < NP; k++) {
        // lane max: pairwise integer max tree (depth 4)
        unsigned t8[8], t4[4];
        #pragma unroll
        for (int j = 0; j < 8; j++) t8[j] = max(lv[2*j], lv[2*j+1]);
        #pragma unroll
        for (int j = 0; j < 4; j++) t4[j] = max(t8[2*j], t8[2*j+1]);
        unsigned wmax = max(max(t4[0], t4[1]), max(t4[2], t4[3]));

        // ONE hardware warp reduction
        wmax = __reduce_max_sync(FULL, wmax);

        // recover owner lane + slot by exact integer equality
        unsigned bits = 0;
        #pragma unroll
        for (int j = 0; j < 15; j++)
            if (lv[j] == wmax) bits |= (1u << j);
        unsigned m = __ballot_sync(FULL, bits != 0);
        int owner = __ffs(m) - 1;
        int slot  = __ffs(bits) - 1;                    // valid on owner
        int gidx  = __shfl_sync(FULL, base + slot * 32 + lane, owner);

        if (lane == 0) {
            g_ckey[(b * CH + ch) * NP + k] = wmax;
            g_cidx[(b * CH + ch) * NP + k] = gidx;
        }

        // poison winner (owner/slot re-derived from gidx)
        int rel = gidx - base;
        if (lane == (rel & 31)) {
            int ps = rel >> 5;
            #pragma unroll
            for (int j = 0; j < 15; j++)
                if (j == ps) lv[j] = 0u;
        }
    }

    // --------- last block to finish performs the merge (no spinning) -------
    __shared__ int s_last;
    __syncthreads();
    if (tid == 0) {
        __threadfence();                                // release candidates
        int c = atomicAdd(&g_done, 1);
        s_last = (c == SBLK - 1);
    }
    __syncthreads();
    if (!s_last) return;

    __threadfence();                                    // acquire candidates
    if (tid == 0) g_done = 0;                           // reset for replay

    const int b2 = warp;                                // 8 warps -> 8 batches

    unsigned cv[10]; int ci[10];
    #pragma unroll
    for (int j = 0; j < 10; j++) {
        int c = j * 32 + lane;
        if (c < NC) { cv[j] = g_ckey[b2 * NC + c]; ci[j] = g_cidx[b2 * NC + c]; }
        else        { cv[j] = 0u;                  ci[j] = -1; }
    }

    float* o_att  = out + PATCH_ELEMS;
    float* o_off  = o_att + BB * NP;
    float* o_samp = o_off + BB * NP * 2;

    #pragma unroll 1
    for (int k = 0; k < NP; k++) {
        unsigned p0 = max(cv[0], cv[1]);
        unsigned p1 = max(cv[2], cv[3]);
        unsigned p2 = max(cv[4], cv[5]);
        unsigned p3 = max(cv[6], cv[7]);
        unsigned p4 = max(cv[8], cv[9]);
        unsigned wmax = max(max(max(p0, p1), max(p2, p3)), p4);

        wmax = __reduce_max_sync(FULL, wmax);

        unsigned bits = 0;
        #pragma unroll
        for (int j = 0; j < 10; j++)
            if (cv[j] == wmax) bits |= (1u << j);
        unsigned m = __ballot_sync(FULL, bits != 0);
        int owner = __ffs(m) - 1;
        int slot  = __ffs(bits) - 1;

        int gi = 0;
        #pragma unroll
        for (int j = 0; j < 10; j++)
            if (j == slot) gi = ci[j];
        gi = __shfl_sync(FULL, gi, owner);

        if (lane == 0) {
            int wi = gi;
            int iy = wi / WATT;
            int ix = wi % WATT;

            o_att[b2 * NP + k] = att[b2 * HW + wi];
            // offsets = (sample + RF/2) * scale = (s+4)*8 exactly
            o_off[(b2 * NP + k) * 2 + 0] = (float)((iy + 4) * 8);
            o_off[(b2 * NP + k) * 2 + 1] = (float)((ix + 4) * 8);
            o_samp[(b2 * NP + k) * 2 + 0] = (float)iy;
            o_samp[(b2 * NP + k) * 2 + 1] = (float)ix;

            int cy = (iy + 4) * 8; if (cy > HH  - PH) cy = HH  - PH;
            int cx = (ix + 4) * 8; if (cx > WHI - PW) cx = WHI - PW;
            g_corners[(b2 * NP + k) * 2 + 0] = cy;
            g_corners[(b2 * NP + k) * 2 + 1] = cx;
        }

        // poison: global indices are unique -> match by ci
        #pragma unroll
        for (int j = 0; j < 10; j++)
            if (ci[j] == gi) cv[j] = 0u;
    }
}

// ---------------------------------------------------------------------------
// Kernel B: patch gather, 8 independent float4s per thread (MLP=8)
// ---------------------------------------------------------------------------
__global__ void __launch_bounds__(256)
gather_kernel(const float* __restrict__ xh,
              float* __restrict__ out)
{
    int t = blockIdx.x * blockDim.x + threadIdx.x;
    if (t >= GSTRIDE) return;

    #pragma unroll
    for (int r = 0; r < GUNROLL; r++) {
        int v = t + r * GSTRIDE;

        int col = v % ROW_VEC;
        int row = v / ROW_VEC;
        int y   = row % PH;
        int pn  = row / PH;              // b*NP + n

        int cy = g_corners[pn * 2 + 0];
        int cx = g_corners[pn * 2 + 1];
        int b  = pn / NP;

        const float4* src = reinterpret_cast<const float4*>(
            xh + ((size_t)(b * HH + cy + y) * WHI + cx) * CC);
        reinterpret_cast<float4*>(out)[v] = src[col];
    }
}

// ---------------------------------------------------------------------------
extern "C" void kernel_launch(void* const* d_in, const int* in_sizes, int n_in,
                              void* d_out, int out_size)
{
    // metadata order: x_low, x_high, attention, uniform_noise
    const float* x_high = (const float*)d_in[1];
    const float* att    = (const float*)d_in[2];
    const float* unoise = (const float*)d_in[3];
    float* out = (float*)d_out;

    score_merge_kernel<<<SBLK, 256>>>(att, unoise, out);

    const int threads = 256;
    const int blocks  = (GSTRIDE + threads - 1) / threads;
    gather_kernel<<<blocks, threads>>>(x_high, out);
}

// round 12
// speedup vs baseline: 1.3617x; 1.3617x over previous
#include <cuda_runtime.h>
#include <math.h>

// Problem constants
#define BB   8
#define HW   14400   // 120*120
#define WATT 120
#define NP   10
#define PH   100
#define PW   100
#define CC   3
#define HH   1024
#define WHI  1024

#define CH    30       // chunks per batch
#define CHUNK 480      // elements per chunk (32 lanes x 15)
#define NC    (CH*NP)  // 300 candidates per batch

// d_out layout (flattened return tuple, all f32):
//   [0, 2400000)            patches (B,N,100,100,3)
//   [2400000, 2400080)      sampled_attention (B,N)
//   [2400080, 2400240)      offsets (B,N,2)
//   [2400240, 2400400)      samples (B,N,2) as float
#define PATCH_ELEMS (BB*NP*PH*PW*CC)   // 2,400,000
#define ROW_VEC     75                 // 300 floats per patch row = 75 float4
#define TOTAL_VEC   (PATCH_ELEMS/4)    // 600,000
#define GUNROLL     8
#define GSTRIDE     (TOTAL_VEC/GUNROLL)  // 75,000

#define SBLK  30       // score blocks (30 x 8 warps = 240 chunks)
#define FULL  0xffffffffu

__device__ int      g_corners[BB * NP * 2];
__device__ unsigned g_ckey[BB * NC];
__device__ int      g_cidx[BB * NC];
__device__ int      g_done = 0;

// order-preserving float->u32 key (all keys here are positive floats);
// poison value 0u is below every real key.
__device__ __forceinline__ unsigned f2key(float f) {
    unsigned x = __float_as_uint(f);
    return x ^ ((unsigned)(((int)x) >> 31) | 0x80000000u);
}

// ---------------------------------------------------------------------------
// Kernel A: score (ratio key, ordering-equivalent to the Gumbel score) +
// per-chunk top-10; the LAST finishing block merges all batches (no spin).
// ---------------------------------------------------------------------------
__global__ void __launch_bounds__(256, 1)
score_merge_kernel(const float* __restrict__ att,
                   const float* __restrict__ u,
                   float* __restrict__ out)
{
    const int tid  = threadIdx.x;
    const int lane = tid & 31;
    const int warp = tid >> 5;

    const int wg   = blockIdx.x * 8 + warp;   // 0..239
    const int b    = wg / CH;
    const int ch   = wg % CH;
    const int base = ch * CHUNK;

    const float* a  = att + b * HW;
    const float* uu = u   + b * HW;

    // ordering key:  log(max(a,1e-20)) - log(-log(clip(u))) is monotonic in
    //   max(a,1e-20) / (-log(clip(u)))   (numerator, denominator both > 0)
    // so key on the ratio directly: 2 MUFU ops instead of 3 logf's.
    unsigned lv[16];
    #pragma unroll
    for (int j = 0; j < 15; j++) {
        int i = base + j * 32 + lane;
        float uv = fminf(fmaxf(uu[i], 1e-6f), 1.0f - 1e-6f);
        float r  = __fdividef(fmaxf(a[i], 1e-20f), -__logf(uv));
        lv[j] = f2key(r);
    }
    lv[15] = 0u;

    #pragma unroll 1
    for (int k = 0; k < NP; k++) {
        // lane max: pairwise integer max tree (depth 4)
        unsigned t8[8], t4[4];
        #pragma unroll
        for (int j = 0; j < 8; j++) t8[j] = max(lv[2*j], lv[2*j+1]);
        #pragma unroll
        for (int j = 0; j < 4; j++) t4[j] = max(t8[2*j], t8[2*j+1]);
        unsigned wmax = max(max(t4[0], t4[1]), max(t4[2], t4[3]));

        // ONE hardware warp reduction
        wmax = __reduce_max_sync(FULL, wmax);

        // recover owner lane + slot by exact integer equality
        unsigned bits = 0;
        #pragma unroll
        for (int j = 0; j < 15; j++)
            if (lv[j] == wmax) bits |= (1u << j);
        unsigned m = __ballot_sync(FULL, bits != 0);
        int owner = __ffs(m) - 1;
        int slot  = __ffs(bits) - 1;                    // valid on owner
        int gidx  = __shfl_sync(FULL, base + slot * 32 + lane, owner);

        if (lane == 0) {
            g_ckey[(b * CH + ch) * NP + k] = wmax;
            g_cidx[(b * CH + ch) * NP + k] = gidx;
        }

        // poison winner (owner/slot re-derived from gidx)
        int rel = gidx - base;
        if (lane == (rel & 31)) {
            int ps = rel >> 5;
            #pragma unroll
            for (int j = 0; j < 15; j++)
                if (j == ps) lv[j] = 0u;
        }
    }

    // --------- last block to finish performs the merge (no spinning) -------
    __shared__ int s_last;
    __syncthreads();
    if (tid == 0) {
        __threadfence();                                // release candidates
        int c = atomicAdd(&g_done, 1);
        s_last = (c == SBLK - 1);
    }
    __syncthreads();
    if (!s_last) return;

    __threadfence();                                    // acquire candidates
    if (tid == 0) g_done = 0;                           // reset for replay

    const int b2 = warp;                                // 8 warps -> 8 batches

    unsigned cv[10]; int ci[10];
    #pragma unroll
    for (int j = 0; j < 10; j++) {
        int c = j * 32 + lane;
        if (c < NC) { cv[j] = g_ckey[b2 * NC + c]; ci[j] = g_cidx[b2 * NC + c]; }
        else        { cv[j] = 0u;                  ci[j] = -1; }
    }

    float* o_att  = out + PATCH_ELEMS;
    float* o_off  = o_att + BB * NP;
    float* o_samp = o_off + BB * NP * 2;

    #pragma unroll 1
    for (int k = 0; k < NP; k++) {
        unsigned p0 = max(cv[0], cv[1]);
        unsigned p1 = max(cv[2], cv[3]);
        unsigned p2 = max(cv[4], cv[5]);
        unsigned p3 = max(cv[6], cv[7]);
        unsigned p4 = max(cv[8], cv[9]);
        unsigned wmax = max(max(max(p0, p1), max(p2, p3)), p4);

        wmax = __reduce_max_sync(FULL, wmax);

        unsigned bits = 0;
        #pragma unroll
        for (int j = 0; j < 10; j++)
            if (cv[j] == wmax) bits |= (1u << j);
        unsigned m = __ballot_sync(FULL, bits != 0);
        int owner = __ffs(m) - 1;
        int slot  = __ffs(bits) - 1;

        int gi = 0;
        #pragma unroll
        for (int j = 0; j < 10; j++)
            if (j == slot) gi = ci[j];
        gi = __shfl_sync(FULL, gi, owner);

        if (lane == 0) {
            int wi = gi;
            int iy = wi / WATT;
            int ix = wi % WATT;

            o_att[b2 * NP + k] = att[b2 * HW + wi];
            // offsets = (sample + RF/2) * scale = (s+4)*8 exactly
            o_off[(b2 * NP + k) * 2 + 0] = (float)((iy + 4) * 8);
            o_off[(b2 * NP + k) * 2 + 1] = (float)((ix + 4) * 8);
            o_samp[(b2 * NP + k) * 2 + 0] = (float)iy;
            o_samp[(b2 * NP + k) * 2 + 1] = (float)ix;

            int cy = (iy + 4) * 8; if (cy > HH  - PH) cy = HH  - PH;
            int cx = (ix + 4) * 8; if (cx > WHI - PW) cx = WHI - PW;
            g_corners[(b2 * NP + k) * 2 + 0] = cy;
            g_corners[(b2 * NP + k) * 2 + 1] = cx;
        }

        // poison: global indices are unique -> match by ci
        #pragma unroll
        for (int j = 0; j < 10; j++)
            if (ci[j] == gi) cv[j] = 0u;
    }
}

// ---------------------------------------------------------------------------
// Kernel B: patch gather, 8 independent float4s per thread (MLP=8)
// ---------------------------------------------------------------------------
__global__ void __launch_bounds__(256)
gather_kernel(const float* __restrict__ xh,
              float* __restrict__ out)
{
    int t = blockIdx.x * blockDim.x + threadIdx.x;
    if (t >= GSTRIDE) return;

    #pragma unroll
    for (int r = 0; r < GUNROLL; r++) {
        int v = t + r * GSTRIDE;

        int col = v % ROW_VEC;
        int row = v / ROW_VEC;
        int y   = row % PH;
        int pn  = row / PH;              // b*NP + n

        int cy = g_corners[pn * 2 + 0];
        int cx = g_corners[pn * 2 + 1];
        int b  = pn / NP;

        const float4* src = reinterpret_cast<const float4*>(
            xh + ((size_t)(b * HH + cy + y) * WHI + cx) * CC);
        reinterpret_cast<float4*>(out)[v] = src[col];
    }
}

// ---------------------------------------------------------------------------
extern "C" void kernel_launch(void* const* d_in, const int* in_sizes, int n_in,
                              void* d_out, int out_size)
{
    // metadata order: x_low, x_high, attention, uniform_noise
    const float* x_high = (const float*)d_in[1];
    const float* att    = (const float*)d_in[2];
    const float* unoise = (const float*)d_in[3];
    float* out = (float*)d_out;

    score_merge_kernel<<<SBLK, 256>>>(att, unoise, out);

    const int threads = 256;
    const int blocks  = (GSTRIDE + threads - 1) / threads;
    gather_kernel<<<blocks, threads>>>(x_high, out);
}

// round 13
// speedup vs baseline: 1.3643x; 1.0019x over previous
#include <cuda_runtime.h>
#include <math.h>

// Problem constants
#define BB   8
#define HW   14400   // 120*120
#define WATT 120
#define NP   10
#define PH   100
#define PW   100
#define CC   3
#define HH   1024
#define WHI  1024

#define CH    30       // chunks per batch
#define CHUNK 480      // elements per chunk (32 lanes x 15)
#define NC    (CH*NP)  // 300 candidates per batch

// d_out layout (flattened return tuple, all f32):
//   [0, 2400000)            patches (B,N,100,100,3)
//   [2400000, 2400080)      sampled_attention (B,N)
//   [2400080, 2400240)      offsets (B,N,2)
//   [2400240, 2400400)      samples (B,N,2) as float
#define PATCH_ELEMS (BB*NP*PH*PW*CC)   // 2,400,000
#define ROW_VEC     75                 // 300 floats per patch row = 75 float4
#define TOTAL_VEC   (PATCH_ELEMS/4)    // 600,000
#define GUNROLL     8
#define GSTRIDE     (TOTAL_VEC/GUNROLL)  // 75,000

#define SBLK  30       // score blocks (30 x 8 warps = 240 chunks)
#define FULL  0xffffffffu

__device__ int      g_corners[BB * NP * 2];
__device__ unsigned g_ckey[BB * NC];
__device__ int      g_cidx[BB * NC];
__device__ int      g_done = 0;

// order-preserving float->u32 key (all keys here are positive floats);
// poison value 0u is below every real key.
__device__ __forceinline__ unsigned f2key(float f) {
    unsigned x = __float_as_uint(f);
    return x ^ ((unsigned)(((int)x) >> 31) | 0x80000000u);
}

// ---------------------------------------------------------------------------
// Kernel A: score (ratio key, ordering-equivalent to the Gumbel score) +
// per-chunk top-10; the LAST finishing block merges all batches (no spin).
// ---------------------------------------------------------------------------
__global__ void __launch_bounds__(256, 1)
score_merge_kernel(const float* __restrict__ att,
                   const float* __restrict__ u,
                   float* __restrict__ out)
{
    const int tid  = threadIdx.x;
    const int lane = tid & 31;
    const int warp = tid >> 5;

    const int wg   = blockIdx.x * 8 + warp;   // 0..239
    const int b    = wg / CH;
    const int ch   = wg % CH;
    const int base = ch * CHUNK;

    const float* a  = att + b * HW;
    const float* uu = u   + b * HW;

    // ordering key:  log(max(a,1e-20)) - log(-log(clip(u))) is monotonic in
    //   max(a,1e-20) / (-log(clip(u)))   (numerator, denominator both > 0)
    // so key on the ratio directly: 2 MUFU ops instead of 3 logf's.
    unsigned lv[16];
    #pragma unroll
    for (int j = 0; j < 15; j++) {
        int i = base + j * 32 + lane;
        float uv = fminf(fmaxf(uu[i], 1e-6f), 1.0f - 1e-6f);
        float r  = __fdividef(fmaxf(a[i], 1e-20f), -__logf(uv));
        lv[j] = f2key(r);
    }
    lv[15] = 0u;

    #pragma unroll 1
    for (int k = 0; k < NP; k++) {
        // lane max: pairwise integer max tree (depth 4)
        unsigned t8[8], t4[4];
        #pragma unroll
        for (int j = 0; j < 8; j++) t8[j] = max(lv[2*j], lv[2*j+1]);
        #pragma unroll
        for (int j = 0; j < 4; j++) t4[j] = max(t8[2*j], t8[2*j+1]);
        unsigned wmax = max(max(t4[0], t4[1]), max(t4[2], t4[3]));

        // ONE hardware warp reduction
        wmax = __reduce_max_sync(FULL, wmax);

        // recover owner lane + slot by exact integer equality
        unsigned bits = 0;
        #pragma unroll
        for (int j = 0; j < 15; j++)
            if (lv[j] == wmax) bits |= (1u << j);
        unsigned m = __ballot_sync(FULL, bits != 0);
        int owner = __ffs(m) - 1;
        int slot  = __ffs(bits) - 1;                    // valid on owner
        int gidx  = __shfl_sync(FULL, base + slot * 32 + lane, owner);

        if (lane == 0) {
            g_ckey[(b * CH + ch) * NP + k] = wmax;
            g_cidx[(b * CH + ch) * NP + k] = gidx;
        }

        // poison winner (owner/slot re-derived from gidx)
        int rel = gidx - base;
        if (lane == (rel & 31)) {
            int ps = rel >> 5;
            #pragma unroll
            for (int j = 0; j < 15; j++)
                if (j == ps) lv[j] = 0u;
        }
    }

    // --------- last block to finish performs the merge (no spinning) -------
    __shared__ int s_last;
    __syncthreads();
    if (tid == 0) {
        __threadfence();                                // release candidates
        int c = atomicAdd(&g_done, 1);
        s_last = (c == SBLK - 1);
    }
    __syncthreads();
    if (!s_last) return;

    __threadfence();                                    // acquire candidates
    if (tid == 0) g_done = 0;                           // reset for replay

    const int b2 = warp;                                // 8 warps -> 8 batches

    unsigned cv[10]; int ci[10];
    #pragma unroll
    for (int j = 0; j < 10; j++) {
        int c = j * 32 + lane;
        if (c < NC) { cv[j] = g_ckey[b2 * NC + c]; ci[j] = g_cidx[b2 * NC + c]; }
        else        { cv[j] = 0u;                  ci[j] = -1; }
    }

    float* o_att  = out + PATCH_ELEMS;
    float* o_off  = o_att + BB * NP;
    float* o_samp = o_off + BB * NP * 2;

    #pragma unroll 1
    for (int k = 0; k < NP; k++) {
        unsigned p0 = max(cv[0], cv[1]);
        unsigned p1 = max(cv[2], cv[3]);
        unsigned p2 = max(cv[4], cv[5]);
        unsigned p3 = max(cv[6], cv[7]);
        unsigned p4 = max(cv[8], cv[9]);
        unsigned wmax = max(max(max(p0, p1), max(p2, p3)), p4);

        wmax = __reduce_max_sync(FULL, wmax);

        unsigned bits = 0;
        #pragma unroll
        for (int j = 0; j < 10; j++)
            if (cv[j] == wmax) bits |= (1u << j);
        unsigned m = __ballot_sync(FULL, bits != 0);
        int owner = __ffs(m) - 1;
        int slot  = __ffs(bits) - 1;

        int gi = 0;
        #pragma unroll
        for (int j = 0; j < 10; j++)
            if (j == slot) gi = ci[j];
        gi = __shfl_sync(FULL, gi, owner);

        if (lane == 0) {
            int wi = gi;
            int iy = wi / WATT;
            int ix = wi % WATT;

            o_att[b2 * NP + k] = att[b2 * HW + wi];
            // offsets = (sample + RF/2) * scale = (s+4)*8 exactly
            o_off[(b2 * NP + k) * 2 + 0] = (float)((iy + 4) * 8);
            o_off[(b2 * NP + k) * 2 + 1] = (float)((ix + 4) * 8);
            o_samp[(b2 * NP + k) * 2 + 0] = (float)iy;
            o_samp[(b2 * NP + k) * 2 + 1] = (float)ix;

            int cy = (iy + 4) * 8; if (cy > HH  - PH) cy = HH  - PH;
            int cx = (ix + 4) * 8; if (cx > WHI - PW) cx = WHI - PW;
            g_corners[(b2 * NP + k) * 2 + 0] = cy;
            g_corners[(b2 * NP + k) * 2 + 1] = cx;
        }

        // poison: global indices are unique -> match by ci
        #pragma unroll
        for (int j = 0; j < 10; j++)
            if (ci[j] == gi) cv[j] = 0u;
    }
}

// ---------------------------------------------------------------------------
// Kernel B: patch gather, 8 independent float4s per thread (MLP=8)
// ---------------------------------------------------------------------------
__global__ void __launch_bounds__(256)
gather_kernel(const float* __restrict__ xh,
              float* __restrict__ out)
{
    int t = blockIdx.x * blockDim.x + threadIdx.x;
    if (t >= GSTRIDE) return;

    #pragma unroll
    for (int r = 0; r < GUNROLL; r++) {
        int v = t + r * GSTRIDE;

        int col = v % ROW_VEC;
        int row = v / ROW_VEC;
        int y   = row % PH;
        int pn  = row / PH;              // b*NP + n

        int cy = g_corners[pn * 2 + 0];
        int cx = g_corners[pn * 2 + 1];
        int b  = pn / NP;

        const float4* src = reinterpret_cast<const float4*>(
            xh + ((size_t)(b * HH + cy + y) * WHI + cx) * CC);
        reinterpret_cast<float4*>(out)[v] = src[col];
    }
}

// ---------------------------------------------------------------------------
extern "C" void kernel_launch(void* const* d_in, const int* in_sizes, int n_in,
                              void* d_out, int out_size)
{
    // metadata order: x_low, x_high, attention, uniform_noise
    const float* x_high = (const float*)d_in[1];
    const float* att    = (const float*)d_in[2];
    const float* unoise = (const float*)d_in[3];
    float* out = (float*)d_out;

    score_merge_kernel<<<SBLK, 256>>>(att, unoise, out);

    const int threads = 256;
    const int blocks  = (GSTRIDE + threads - 1) / threads;
    gather_kernel<<<blocks, threads>>>(x_high, out);
}